// round 7
// baseline (speedup 1.0000x reference)
#include <cuda_runtime.h>
#include <cuda_bf16.h>
#include <math.h>

// out [16,4096,513] f32. Smem-staged variant: every DRAM access on both sides
// is fully aligned/coalesced. CTA owns 16 input rows (16*512 floats, pure
// LDG.128) staged into padded smem (row stride 520 floats -> STS.128
// conflict-free), plus 16 pe values. Output region per CTA = 16*513 = 8208
// floats, dense + 16B-aligned (8208*4 % 16 == 0), written as stride-1
// coalesced STG.32 fed by conflict-free LDS.
// grid = 65536/16 = 4096 CTAs, 256 threads.

#define S_DIM 4096
#define D_DIM 512
#define OD    513u
#define ROWS  16
#define SROW  520            // padded smem row stride (floats), 16B-aligned
#define PI_F 3.14159265358979323846f

__device__ __forceinline__ float pe_val(unsigned row, const int* __restrict__ lengths) {
    const unsigned b = row >> 12;
    const unsigned s = row & (S_DIM - 1);
    const int len = __ldg(&lengths[b]);
    float pe = 0.0f;
    if ((int)s < len) {
        float fl = fmaxf((float)len, 1.0f);
        pe = cosf((float)s / fl * PI_F);
    }
    return pe;
}

__global__ __launch_bounds__(256) void concat_pe_smem_kernel(
    const float* __restrict__ inp,
    const int* __restrict__ lengths,
    float* __restrict__ out)
{
    __shared__ float smem[ROWS * SROW];          // 33280 B

    const unsigned t    = threadIdx.x;
    const unsigned row0 = blockIdx.x * ROWS;

    // Phase 1: aligned LDG.128 of 16 rows -> padded smem via STS.128.
    const float4* src = reinterpret_cast<const float4*>(inp + (size_t)row0 * D_DIM);
    #pragma unroll
    for (int i = 0; i < 8; i++) {
        unsigned v  = i * 256u + t;              // 0..2047 float4 index
        unsigned r  = v >> 7;                    // /128 f4 per row
        unsigned c4 = v & 127u;
        float4 x;
        x.x = __ldcs(&reinterpret_cast<const float*>(src)[v * 4u + 0]);
        x.y = __ldcs(&reinterpret_cast<const float*>(src)[v * 4u + 1]);
        x.z = __ldcs(&reinterpret_cast<const float*>(src)[v * 4u + 2]);
        x.w = __ldcs(&reinterpret_cast<const float*>(src)[v * 4u + 3]);
        *reinterpret_cast<float4*>(&smem[r * SROW + c4 * 4u]) = x;
    }
    if (t < ROWS) {
        smem[t * SROW + D_DIM] = pe_val(row0 + t, lengths);
    }
    __syncthreads();

    // Phase 2: dense aligned output region, stride-1 coalesced STG.32.
    float* obase = out + (size_t)blockIdx.x * (ROWS * OD);   // 8208 floats
    #pragma unroll
    for (int i = 0; i < 33; i++) {
        unsigned f = i * 256u + t;               // 0..8447
        if (f < ROWS * OD) {
            unsigned r = f / OD;                 // mulhi
            unsigned c = f - r * OD;
            __stcs(&obase[f], smem[r * SROW + c]);
        }
    }
}

extern "C" void kernel_launch(void* const* d_in, const int* in_sizes, int n_in,
                              void* d_out, int out_size) {
    const float* inp = (const float*)d_in[0];
    const int* lengths = (const int*)d_in[1];
    float* out = (float*)d_out;

    dim3 grid(S_DIM * 16 / ROWS);                // 4096 CTAs
    dim3 block(256);
    concat_pe_smem_kernel<<<grid, block>>>(inp, lengths, out);
}

// round 8
// speedup vs baseline: 1.1768x; 1.1768x over previous
#include <cuda_runtime.h>
#include <cuda_bf16.h>
#include <math.h>

// out [16,4096,513] f32 flat = 33,619,968 floats = 8,404,992 float4s.
// CONVERGED kernel (R5): aligned float4 streaming stores over the flat output;
// scalar streaming loads dedup'd via L2 sectors; unroll 4 per thread.
// Measured: 40.26us kernel, DRAM 68.7% — at the HBM mixed R/W stream ceiling
// (5 structural variants all bracket ~68%; see round ledger).
// grid = 8,404,992 / (256*4) = 8208 CTAs exactly.

#define S_DIM 4096
#define D_DIM 512
#define OD    513u
#define PI_F 3.14159265358979323846f
#define UNROLL 4

__device__ __forceinline__ float pe_val(unsigned row, const int* __restrict__ lengths) {
    const unsigned b = row >> 12;
    const unsigned s = row & (S_DIM - 1);
    const int len = __ldg(&lengths[b]);
    float pe = 0.0f;
    if ((int)s < len) {
        float fl = fmaxf((float)len, 1.0f);
        pe = cosf((float)s / fl * PI_F);
    }
    return pe;
}

__device__ __forceinline__ float4 gather4(unsigned idx,
                                          const float* __restrict__ inp,
                                          const int* __restrict__ lengths) {
    const unsigned f   = idx * 4u;
    const unsigned row = f / OD;            // mulhi
    const unsigned col = f - row * OD;
    float4 v;
    if (col <= (unsigned)(D_DIM - 4)) {
        const float* src = inp + (size_t)row * D_DIM + col;
        v.x = __ldcs(src + 0);
        v.y = __ldcs(src + 1);
        v.z = __ldcs(src + 2);
        v.w = __ldcs(src + 3);
    } else {
        float tmp[4];
        #pragma unroll
        for (int k = 0; k < 4; k++) {
            unsigned ck = col + (unsigned)k;
            if (ck < (unsigned)D_DIM) {
                tmp[k] = __ldcs(inp + (size_t)row * D_DIM + ck);
            } else if (ck == (unsigned)D_DIM) {
                tmp[k] = pe_val(row, lengths);
            } else {
                tmp[k] = __ldcs(inp + (size_t)(row + 1u) * D_DIM + (ck - OD));
            }
        }
        v.x = tmp[0]; v.y = tmp[1]; v.z = tmp[2]; v.w = tmp[3];
    }
    return v;
}

__global__ __launch_bounds__(256) void concat_pe_u4_kernel(
    const float* __restrict__ inp,
    const int* __restrict__ lengths,
    float* __restrict__ out)
{
    const unsigned base = blockIdx.x * (256u * UNROLL) + threadIdx.x;

    float4 v[UNROLL];
    #pragma unroll
    for (int k = 0; k < UNROLL; k++)
        v[k] = gather4(base + k * 256u, inp, lengths);

    float4* o = reinterpret_cast<float4*>(out);
    #pragma unroll
    for (int k = 0; k < UNROLL; k++)
        __stcs(o + base + k * 256u, v[k]);
}

extern "C" void kernel_launch(void* const* d_in, const int* in_sizes, int n_in,
                              void* d_out, int out_size) {
    const float* inp = (const float*)d_in[0];
    const int* lengths = (const int*)d_in[1];
    float* out = (float*)d_out;

    // 8,404,992 float4s / (256 threads * 4) = 8208 CTAs exactly.
    dim3 grid(8208);
    dim3 block(256);
    concat_pe_u4_kernel<<<grid, block>>>(inp, lengths, out);
}

// round 9
// speedup vs baseline: 1.1834x; 1.0056x over previous
#include <cuda_runtime.h>
#include <cuda_bf16.h>
#include <math.h>

// FINAL kernel (= R0, best harness-measured dur_us: 43.49us).
// inp [B=16, S=4096, D=512] f32, lengths [16] i32
// out [B, S, 513] f32 : out[b,s,0:512] = inp[b,s,:]
//                       out[b,s,512]   = (s < len[b]) ? cos(s/max(len,1)*pi) : 0
//
// Pure bandwidth problem (~269 MB, irreducible 1R+1W per byte). Measured at the
// HBM mixed read/write stream ceiling: 6.5+ TB/s wallclock, DRAM ~68% busy.
// Five structural variants (store-aligned, load-aligned, unrolled, write-back,
// smem-staged) all bracket this wall; this variant wins harness (NAT-clock)
// timing — full occupancy, one float4 load + 4 coalesced stores per thread.

#define B_DIM 16
#define S_DIM 4096
#define D_DIM 512
#define PI_F 3.14159265358979323846f

__global__ __launch_bounds__(128) void concat_pe_kernel(
    const float* __restrict__ inp,
    const int* __restrict__ lengths,
    float* __restrict__ out)
{
    const int row = blockIdx.x;               // 0 .. B*S-1
    const int tid = threadIdx.x;              // 0 .. 127
    const int s = row & (S_DIM - 1);
    const int b = row >> 12;                  // row / 4096

    // Vector load: 128 threads x float4 = 512 floats, perfectly aligned.
    const float4* src = reinterpret_cast<const float4*>(inp + (size_t)row * D_DIM);
    float4 v = src[tid];

    // Output row base: (size_t)row * 513 — only 4B aligned, use scalar stores.
    float* dst = out + (size_t)row * (D_DIM + 1);
    const int c = tid * 4;
    dst[c + 0] = v.x;
    dst[c + 1] = v.y;
    dst[c + 2] = v.z;
    dst[c + 3] = v.w;

    if (tid == 0) {
        const int len = lengths[b];
        float pe = 0.0f;
        if (s < len) {
            float fl = fmaxf((float)len, 1.0f);
            pe = cosf((float)s / fl * PI_F);
        }
        dst[D_DIM] = pe;
    }
}

extern "C" void kernel_launch(void* const* d_in, const int* in_sizes, int n_in,
                              void* d_out, int out_size) {
    const float* inp = (const float*)d_in[0];
    const int* lengths = (const int*)d_in[1];
    float* out = (float*)d_out;

    dim3 grid(B_DIM * S_DIM);  // 65536 rows
    dim3 block(128);
    concat_pe_kernel<<<grid, block>>>(inp, lengths, out);
}

// round 10
// speedup vs baseline: 1.2401x; 1.0479x over previous
#include <cuda_runtime.h>
#include <cuda_bf16.h>
#include <math.h>

// FINAL: R0 structure (one 128-thread CTA per row, best harness-overhead
// profile across runs) + streaming cache hints on both load and store.
// inp [16,4096,512] f32, lengths [16] i32 -> out [16,4096,513] f32.
// Pure-bandwidth copy (~269 MB, 1R+1W per byte); measured converged at the
// HBM mixed R/W ceiling: ~40.5-41.3us kernel, DRAM ~68%, 6.6 TB/s wallclock.
// 5 structural variants bracket this wall (store/load alignment, unroll,
// write-back, smem-staged) — none beats it.

#define B_DIM 16
#define S_DIM 4096
#define D_DIM 512
#define PI_F 3.14159265358979323846f

__global__ __launch_bounds__(128) void concat_pe_kernel(
    const float* __restrict__ inp,
    const int* __restrict__ lengths,
    float* __restrict__ out)
{
    const int row = blockIdx.x;               // 0 .. B*S-1
    const int tid = threadIdx.x;              // 0 .. 127
    const int s = row & (S_DIM - 1);
    const int b = row >> 12;                  // row / 4096

    // Vector streaming load: 128 threads x float4 = 512 floats, 16B-aligned.
    const float4* src = reinterpret_cast<const float4*>(inp + (size_t)row * D_DIM);
    float4 v = __ldcs(src + tid);

    // Output row base: row * 513 floats — 4B-aligned, coalesced scalar stores.
    float* dst = out + (size_t)row * (D_DIM + 1);
    const int c = tid * 4;
    __stcs(dst + c + 0, v.x);
    __stcs(dst + c + 1, v.y);
    __stcs(dst + c + 2, v.z);
    __stcs(dst + c + 3, v.w);

    if (tid == 0) {
        const int len = __ldg(&lengths[b]);
        float pe = 0.0f;
        if (s < len) {
            float fl = fmaxf((float)len, 1.0f);
            pe = cosf((float)s / fl * PI_F);
        }
        __stcs(dst + D_DIM, pe);
    }
}

extern "C" void kernel_launch(void* const* d_in, const int* in_sizes, int n_in,
                              void* d_out, int out_size) {
    const float* inp = (const float*)d_in[0];
    const int* lengths = (const int*)d_in[1];
    float* out = (float*)d_out;

    dim3 grid(B_DIM * S_DIM);  // 65536 rows
    dim3 block(128);
    concat_pe_kernel<<<grid, block>>>(inp, lengths, out);
}